// round 13
// baseline (speedup 1.0000x reference)
#include <cuda_runtime.h>
#include <cuda_bf16.h>
#include <cstdint>

// Problem constants
#define BB   16
#define N1V  4096
#define N2V  1024
#define C2V  256
#define OUTV 256
#define KV   4096

// ---------------- scratch (static device globals; no allocs) ----------------
__device__ int   g_idx[BB * N1V * 3];
__device__ float g_w  [BB * N1V * 3];
__device__ __nv_bfloat16 g_Bh[(size_t)BB * KV * C2V];   // 16 MB, [b][k][c] hi
__device__ __nv_bfloat16 g_Bl[(size_t)BB * KV * C2V];   // 16 MB, [b][k][c] lo
__device__ __nv_bfloat16 g_Wh[OUTV * KV];               // 2 MB
__device__ __nv_bfloat16 g_Wl[OUTV * KV];               // 2 MB
__device__ float g_part[4 * BB * 2 * 2 * 128 * 128];    // 16 MB split-K partials
__device__ float g_z[BB * OUTV * C2V];                  // 4 MB [b][o][c]
__device__ float g_psum[128 * C2V];
__device__ float g_psq [128 * C2V];
__device__ float g_scale[C2V];
__device__ float g_shift[C2V];

__device__ __forceinline__ uint32_t smem_u32(const void* p) {
    uint32_t a;
    asm("{ .reg .u64 t; cvta.to.shared.u64 t, %1; cvt.u32.u64 %0, t; }" : "=r"(a) : "l"(p));
    return a;
}

// ---------------- Stage 0: split W1 to bf16 hi/lo ----------------
__global__ __launch_bounds__(256) void wsplit_kernel(const float* __restrict__ W1)
{
    const int i = blockIdx.x * 256 + threadIdx.x;   // 1M elems
    float v = W1[i];
    __nv_bfloat16 h = __float2bfloat16(v);
    g_Wh[i] = h;
    g_Wl[i] = __float2bfloat16(v - __bfloat162float(h));
}

// ---------------- Stage 1: top-3 NN, 2 queries/thread, guarded branchless insert ----------------
// grid: 16 batches x 8 chunks = 128 blocks, 256 threads; each thread owns queries n0 and n0+256.
__global__ __launch_bounds__(256) void top3_kernel(
    const float* __restrict__ xyz1, const float* __restrict__ xyz2)
{
    __shared__ float4 s[N2V];   // 16 KB
    const int b     = blockIdx.x >> 3;
    const int chunk = blockIdx.x & 7;

    const float* p2 = xyz2 + (size_t)b * N2V * 3;
    for (int j = threadIdx.x; j < N2V; j += 256) {
        float x = p2[j * 3 + 0], y = p2[j * 3 + 1], z = p2[j * 3 + 2];
        s[j] = make_float4(x, y, z, x * x + y * y + z * z);
    }
    __syncthreads();

    const int n0 = chunk * 512 + threadIdx.x;
    const int n1 = n0 + 256;
    const float* p1a = xyz1 + ((size_t)b * N1V + n0) * 3;
    const float* p1b = xyz1 + ((size_t)b * N1V + n1) * 3;
    const float ax = p1a[0], ay = p1a[1], az = p1a[2];
    const float bx = p1b[0], by = p1b[1], bz = p1b[2];
    const float asq = ax * ax + ay * ay + az * az;
    const float bsq = bx * bx + by * by + bz * bz;

    float A0 = 1e30f, A1 = 1e30f, A2 = 1e30f;
    float B0 = 1e30f, B1 = 1e30f, B2 = 1e30f;
    int   Ai0 = 0, Ai1 = 0, Ai2 = 0;
    int   Bi0 = 0, Bi1 = 0, Bi2 = 0;

    #pragma unroll 4
    for (int j = 0; j < N2V; j++) {
        float4 q = s[j];
        float dA = asq + q.w - 2.0f * (ax * q.x + ay * q.y + az * q.z);
        float dB = bsq + q.w - 2.0f * (bx * q.x + by * q.y + bz * q.z);
        if (dA < A2) {
            bool c1 = dA < A1, c0 = dA < A0;
            A2 = c1 ? A1 : dA;             Ai2 = c1 ? Ai1 : j;
            A1 = c0 ? A0 : (c1 ? dA : A1); Ai1 = c0 ? Ai0 : (c1 ? j : Ai1);
            A0 = c0 ? dA : A0;             Ai0 = c0 ? j : Ai0;
        }
        if (dB < B2) {
            bool c1 = dB < B1, c0 = dB < B0;
            B2 = c1 ? B1 : dB;             Bi2 = c1 ? Bi1 : j;
            B1 = c0 ? B0 : (c1 ? dB : B1); Bi1 = c0 ? Bi0 : (c1 ? j : Bi1);
            B0 = c0 ? dB : B0;             Bi0 = c0 ? j : Bi0;
        }
    }

    {
        const float r0 = 1.0f / (A0 + 1e-8f);
        const float r1 = 1.0f / (A1 + 1e-8f);
        const float r2 = 1.0f / (A2 + 1e-8f);
        const float inv = 1.0f / (r0 + r1 + r2);
        const int base = ((b * N1V) + n0) * 3;
        g_idx[base + 0] = Ai0; g_idx[base + 1] = Ai1; g_idx[base + 2] = Ai2;
        g_w  [base + 0] = r0 * inv; g_w[base + 1] = r1 * inv; g_w[base + 2] = r2 * inv;
    }
    {
        const float r0 = 1.0f / (B0 + 1e-8f);
        const float r1 = 1.0f / (B1 + 1e-8f);
        const float r2 = 1.0f / (B2 + 1e-8f);
        const float inv = 1.0f / (r0 + r1 + r2);
        const int base = ((b * N1V) + n1) * 3;
        g_idx[base + 0] = Bi0; g_idx[base + 1] = Bi1; g_idx[base + 2] = Bi2;
        g_w  [base + 0] = r0 * inv; g_w[base + 1] = r1 * inv; g_w[base + 2] = r2 * inv;
    }
}

// ---------------- Stage 2: gather interpolation -> bf16 hi/lo, [b][k][c] ----------------
__global__ __launch_bounds__(256) void interp_kernel(const float* __restrict__ x2)
{
    const int row = blockIdx.x * 4 + (threadIdx.x >> 6);   // b*N1 + n
    const int c4  = threadIdx.x & 63;
    const int b   = row >> 12;
    const int base = row * 3;

    const int i0 = g_idx[base + 0], i1 = g_idx[base + 1], i2 = g_idx[base + 2];
    const float w0 = g_w[base + 0], w1 = g_w[base + 1], w2 = g_w[base + 2];

    const float4* xb = (const float4*)(x2 + (size_t)b * N2V * C2V);
    float4 a = xb[i0 * 64 + c4];
    float4 p = xb[i1 * 64 + c4];
    float4 q = xb[i2 * 64 + c4];

    float4 v;
    v.x = w0 * a.x + w1 * p.x + w2 * q.x;
    v.y = w0 * a.y + w1 * p.y + w2 * q.y;
    v.z = w0 * a.z + w1 * p.z + w2 * q.z;
    v.w = w0 * a.w + w1 * p.w + w2 * q.w;

    __nv_bfloat162 h0 = __floats2bfloat162_rn(v.x, v.y);
    __nv_bfloat162 h1 = __floats2bfloat162_rn(v.z, v.w);
    float lx = v.x - __bfloat162float(h0.x);
    float ly = v.y - __bfloat162float(h0.y);
    float lz = v.z - __bfloat162float(h1.x);
    float lw = v.w - __bfloat162float(h1.y);
    __nv_bfloat162 l0 = __floats2bfloat162_rn(lx, ly);
    __nv_bfloat162 l1 = __floats2bfloat162_rn(lz, lw);

    const size_t o2 = (size_t)row * 128 + c4 * 2;
    ((__nv_bfloat162*)g_Bh)[o2 + 0] = h0;
    ((__nv_bfloat162*)g_Bh)[o2 + 1] = h1;
    ((__nv_bfloat162*)g_Bl)[o2 + 0] = l0;
    ((__nv_bfloat162*)g_Bl)[o2 + 1] = l1;
}

// ---------------- Stage 3: mma.sync bf16x3 GEMM, split-K=4, 3-stage pipeline ----------------
// grid (ct=2, ot=2, z=64: b=z&15, kc=z>>4), 256 threads, 2 CTAs/SM.
// CTA tile: M=128, N=128, K=1024, k-chunks of 32; ONE barrier per k-iteration.
#define KT     32
#define NIT    32            // 1024 / KT
#define A_STR  80            // bytes per A smem row (64 data + 16 pad)
#define B_STR  272           // bytes per B smem row (256 data + 16 pad)
#define AS_SZ  (128 * A_STR) // 10240
#define BS_SZ  (KT * B_STR)  // 8704
#define STAGE  (2 * AS_SZ + 2 * BS_SZ)  // 37888
#define NSTG   3
#define SMEMT  (NSTG * STAGE)           // 113664

__device__ __forceinline__ void ldsm_x4(uint32_t* r, uint32_t addr) {
    asm volatile("ldmatrix.sync.aligned.m8n8.x4.shared.b16 {%0,%1,%2,%3}, [%4];"
                 : "=r"(r[0]), "=r"(r[1]), "=r"(r[2]), "=r"(r[3]) : "r"(addr));
}
__device__ __forceinline__ void ldsm_x4t(uint32_t* r, uint32_t addr) {
    asm volatile("ldmatrix.sync.aligned.m8n8.x4.trans.shared.b16 {%0,%1,%2,%3}, [%4];"
                 : "=r"(r[0]), "=r"(r[1]), "=r"(r[2]), "=r"(r[3]) : "r"(addr));
}
__device__ __forceinline__ void mma_bf16(float* d, const uint32_t* a, const uint32_t* b) {
    asm volatile(
        "mma.sync.aligned.m16n8k16.row.col.f32.bf16.bf16.f32 "
        "{%0,%1,%2,%3}, {%4,%5,%6,%7}, {%8,%9}, {%0,%1,%2,%3};"
        : "+f"(d[0]), "+f"(d[1]), "+f"(d[2]), "+f"(d[3])
        : "r"(a[0]), "r"(a[1]), "r"(a[2]), "r"(a[3]), "r"(b[0]), "r"(b[1]));
}
__device__ __forceinline__ void cp16(uint32_t saddr, const void* gaddr) {
    asm volatile("cp.async.cg.shared.global [%0], [%1], 16;" :: "r"(saddr), "l"(gaddr));
}

__global__ __launch_bounds__(256, 2) void gemm_mma_kernel()
{
    extern __shared__ __align__(128) char smem[];
    const uint32_t sb = smem_u32(smem);
    const int tid = threadIdx.x;
    const int wid = tid >> 5, lane = tid & 31;
    const int ct = blockIdx.x, ot = blockIdx.y;
    const int b  = blockIdx.z & 15, kc = blockIdx.z >> 4;
    const int k0 = kc * 1024;

    const __nv_bfloat16* Ahg = g_Wh + (size_t)(ot * 128) * KV + k0;
    const __nv_bfloat16* Alg = g_Wl + (size_t)(ot * 128) * KV + k0;
    const __nv_bfloat16* Bhg = g_Bh + (size_t)b * KV * C2V + (size_t)k0 * C2V + ct * 128;
    const __nv_bfloat16* Blg = g_Bl + (size_t)b * KV * C2V + (size_t)k0 * C2V + ct * 128;

    float acc[4][4][4];
    #pragma unroll
    for (int i = 0; i < 4; i++)
        #pragma unroll
        for (int j = 0; j < 4; j++)
            #pragma unroll
            for (int q = 0; q < 4; q++) acc[i][j][q] = 0.f;

    auto load_stage = [&](int it, int buf) {
        const int kb = it * KT;
        const uint32_t st = sb + buf * STAGE;
        #pragma unroll
        for (int t = 0; t < 8; t++) {
            const int ch = t * 256 + tid;
            if (ch < 512) {                       // Ah
                const int row = ch >> 2, ko = ch & 3;
                cp16(st + row * A_STR + ko * 16,
                     Ahg + (size_t)row * KV + kb + ko * 8);
            } else if (ch < 1024) {               // Al
                const int c2 = ch - 512;
                const int row = c2 >> 2, ko = c2 & 3;
                cp16(st + AS_SZ + row * A_STR + ko * 16,
                     Alg + (size_t)row * KV + kb + ko * 8);
            } else if (ch < 1536) {               // Bh
                const int c2 = ch - 1024;
                const int row = c2 >> 4, co = c2 & 15;
                cp16(st + 2 * AS_SZ + row * B_STR + co * 16,
                     Bhg + (size_t)(kb + row) * C2V + co * 8);
            } else {                              // Bl
                const int c2 = ch - 1536;
                const int row = c2 >> 4, co = c2 & 15;
                cp16(st + 2 * AS_SZ + BS_SZ + row * B_STR + co * 16,
                     Blg + (size_t)(kb + row) * C2V + co * 8);
            }
        }
        asm volatile("cp.async.commit_group;" ::: "memory");
    };

    load_stage(0, 0);
    load_stage(1, 1);

    const int wm = (wid >> 2) * 64;
    const int wn = (wid & 3) * 32;

    const int a_row = (lane & 15);
    const int a_ko  = ((lane >> 4) & 1) * 8;
    const int b_kro = (lane & 15);
    const int b_nco = wn + ((lane >> 4) & 1) * 8;

    int buf = 0;
    for (int it = 0; it < NIT; it++) {
        if (it == NIT - 1) asm volatile("cp.async.wait_group 0;" ::: "memory");
        else               asm volatile("cp.async.wait_group 1;" ::: "memory");
        __syncthreads();   // stage `buf` ready; all warps done reading stage being reloaded

        const uint32_t st = sb + buf * STAGE;
        #pragma unroll
        for (int ks = 0; ks < KT / 16; ks++) {
            const int koff = ks * 16;
            uint32_t Ah[4][4], Al[4][4];
            #pragma unroll
            for (int mi = 0; mi < 4; mi++) {
                const uint32_t arow = wm + mi * 16 + a_row;
                const uint32_t kcol = koff + a_ko;
                ldsm_x4(Ah[mi], st + arow * A_STR + kcol * 2);
                ldsm_x4(Al[mi], st + AS_SZ + arow * A_STR + kcol * 2);
            }
            uint32_t Bf[2][4];
            #pragma unroll
            for (int g = 0; g < 2; g++) {
                const uint32_t krow = koff + b_kro;
                const uint32_t ncol = b_nco + g * 16;
                ldsm_x4t(Bf[g], st + 2 * AS_SZ + krow * B_STR + ncol * 2);
            }
            #pragma unroll
            for (int mi = 0; mi < 4; mi++)
                #pragma unroll
                for (int nj = 0; nj < 4; nj++) {
                    mma_bf16(acc[mi][nj], Ah[mi], &Bf[nj >> 1][(nj & 1) * 2]);
                    mma_bf16(acc[mi][nj], Al[mi], &Bf[nj >> 1][(nj & 1) * 2]);
                }
            #pragma unroll
            for (int g = 0; g < 2; g++) {
                const uint32_t krow = koff + b_kro;
                const uint32_t ncol = b_nco + g * 16;
                ldsm_x4t(Bf[g], st + 2 * AS_SZ + BS_SZ + krow * B_STR + ncol * 2);
            }
            #pragma unroll
            for (int mi = 0; mi < 4; mi++)
                #pragma unroll
                for (int nj = 0; nj < 4; nj++)
                    mma_bf16(acc[mi][nj], Ah[mi], &Bf[nj >> 1][(nj & 1) * 2]);
        }

        if (it + 2 < NIT) {
            int nb = buf + 2; if (nb >= NSTG) nb -= NSTG;
            load_stage(it + 2, nb);
        }
        buf = (buf + 1 == NSTG) ? 0 : buf + 1;
    }

    float* pp = g_part + ((((size_t)kc * 16 + b) * 2 + ot) * 2 + ct) * 16384;
    const int lr = lane >> 2, lc = (lane & 3) * 2;
    #pragma unroll
    for (int mi = 0; mi < 4; mi++) {
        const int r0 = wm + mi * 16 + lr;
        #pragma unroll
        for (int nj = 0; nj < 4; nj++) {
            const int c = wn + nj * 8 + lc;
            *(float2*)(pp + (size_t)r0 * 128 + c)       = make_float2(acc[mi][nj][0], acc[mi][nj][1]);
            *(float2*)(pp + (size_t)(r0 + 8) * 128 + c) = make_float2(acc[mi][nj][2], acc[mi][nj][3]);
        }
    }
}

// ---------------- Stage 3b (fused): split-K reduce + bias -> g_z, plus BN partial sums ----------------
__global__ __launch_bounds__(256) void reduce_bnpart_kernel(const float* __restrict__ b1)
{
    const int c = threadIdx.x;
    const int r0 = blockIdx.x * 32;
    float s = 0.f, sq = 0.f;
    #pragma unroll 4
    for (int r = r0; r < r0 + 32; r++) {
        const int b = r >> 8, o = r & 255;
        const size_t inner = ((size_t)(o >> 7) * 2 + (c >> 7)) * 16384
                           + (size_t)(o & 127) * 128 + (c & 127);
        float v = b1[o];
        #pragma unroll
        for (int kc = 0; kc < 4; kc++)
            v += g_part[((size_t)kc * 16 + b) * 65536 + inner];
        g_z[(size_t)r * C2V + c] = v;
        s += v; sq += v * v;
    }
    g_psum[blockIdx.x * C2V + c] = s;
    g_psq [blockIdx.x * C2V + c] = sq;
}

// ---------------- Stage 4: BN finalize + apply ----------------
__global__ __launch_bounds__(256) void bn_final_kernel(
    const float* __restrict__ gamma, const float* __restrict__ beta)
{
    const int c = threadIdx.x;
    float s = 0.f, sq = 0.f;
    #pragma unroll
    for (int i = 0; i < 128; i++) { s += g_psum[i * C2V + c]; sq += g_psq[i * C2V + c]; }
    const float mean = s * (1.0f / 4096.0f);
    const float var  = sq * (1.0f / 4096.0f) - mean * mean;
    const float rstd = rsqrtf(var + 1e-5f);
    const float a = gamma[c] * rstd;
    g_scale[c] = a;
    g_shift[c] = beta[c] - mean * a;
}

__global__ __launch_bounds__(256) void bn_apply_kernel(float* __restrict__ out)
{
    const int i = blockIdx.x * 256 + threadIdx.x;
    const int c = i & 255;
    float v = fmaf(g_z[i], g_scale[c], g_shift[c]);
    out[i] = fmaxf(v, 0.0f);
}

// ---------------- launch ----------------
extern "C" void kernel_launch(void* const* d_in, const int* in_sizes, int n_in,
                              void* d_out, int out_size)
{
    const float* x2    = (const float*)d_in[1];
    const float* xyz1  = (const float*)d_in[2];
    const float* xyz2  = (const float*)d_in[3];
    const float* W1    = (const float*)d_in[4];
    const float* b1    = (const float*)d_in[5];
    const float* gamma = (const float*)d_in[6];
    const float* beta  = (const float*)d_in[7];
    float* out = (float*)d_out;

    static bool attr_set = false;
    if (!attr_set) {
        cudaFuncSetAttribute(gemm_mma_kernel,
                             cudaFuncAttributeMaxDynamicSharedMemorySize, SMEMT);
        attr_set = true;
    }

    top3_kernel<<<BB * 8, 256>>>(xyz1, xyz2);
    wsplit_kernel<<<(OUTV * KV) / 256, 256>>>(W1);
    interp_kernel<<<(BB * N1V) / 4, 256>>>(x2);

    dim3 ggrid(2, 2, 64);
    gemm_mma_kernel<<<ggrid, 256, SMEMT>>>();

    reduce_bnpart_kernel<<<128, 256>>>(b1);
    bn_final_kernel<<<1, 256>>>(gamma, beta);
    bn_apply_kernel<<<(BB * OUTV * C2V) / 256, 256>>>(out);
}

// round 14
// speedup vs baseline: 1.1967x; 1.1967x over previous
#include <cuda_runtime.h>
#include <cuda_bf16.h>
#include <cstdint>

// Problem constants
#define BB   16
#define N1V  4096
#define N2V  1024
#define C2V  256
#define OUTV 256
#define KV   4096

// ---------------- scratch (static device globals; no allocs) ----------------
__device__ int   g_idx[BB * N1V * 3];
__device__ float g_w  [BB * N1V * 3];
__device__ __nv_bfloat16 g_Bh[(size_t)BB * KV * C2V];   // 16 MB, [b][k][c] hi
__device__ __nv_bfloat16 g_Bl[(size_t)BB * KV * C2V];   // 16 MB, [b][k][c] lo
__device__ __nv_bfloat16 g_Wh[OUTV * KV];               // 2 MB
__device__ __nv_bfloat16 g_Wl[OUTV * KV];               // 2 MB
__device__ float g_part[4 * BB * 2 * 2 * 128 * 128];    // 16 MB split-K partials
__device__ float g_z[BB * OUTV * C2V];                  // 4 MB [b][o][c]
__device__ float g_psum[128 * C2V];
__device__ float g_psq [128 * C2V];
__device__ float g_scale[C2V];
__device__ float g_shift[C2V];

__device__ __forceinline__ uint32_t smem_u32(const void* p) {
    uint32_t a;
    asm("{ .reg .u64 t; cvta.to.shared.u64 t, %1; cvt.u32.u64 %0, t; }" : "=r"(a) : "l"(p));
    return a;
}

// ---------------- Stage 0: split W1 to bf16 hi/lo ----------------
__global__ __launch_bounds__(256) void wsplit_kernel(const float* __restrict__ W1)
{
    const int i = blockIdx.x * 256 + threadIdx.x;   // 1M elems
    float v = W1[i];
    __nv_bfloat16 h = __float2bfloat16(v);
    g_Wh[i] = h;
    g_Wl[i] = __float2bfloat16(v - __bfloat162float(h));
}

// ---------------- Stage 1: top-3 NN (one query/thread; SEL insert under rare guard) ----------------
// grid: BB * 16 = 256 blocks, 256 threads. Each thread owns one query row.
__global__ __launch_bounds__(256) void top3_kernel(
    const float* __restrict__ xyz1, const float* __restrict__ xyz2)
{
    __shared__ float4 s[N2V];   // 16 KB
    const int b     = blockIdx.x >> 4;
    const int chunk = blockIdx.x & 15;

    const float* p2 = xyz2 + (size_t)b * N2V * 3;
    for (int j = threadIdx.x; j < N2V; j += 256) {
        float x = p2[j * 3 + 0], y = p2[j * 3 + 1], z = p2[j * 3 + 2];
        s[j] = make_float4(x, y, z, x * x + y * y + z * z);
    }
    __syncthreads();

    const int n = chunk * 256 + threadIdx.x;
    const float* p1 = xyz1 + ((size_t)b * N1V + n) * 3;
    const float x = p1[0], y = p1[1], z = p1[2];
    const float nsq = x * x + y * y + z * z;

    float d0 = 1e30f, d1 = 1e30f, d2 = 1e30f;
    int   i0 = 0, i1 = 0, i2 = 0;

    #pragma unroll 8
    for (int j = 0; j < N2V; j++) {
        float4 q = s[j];
        float dot = x * q.x + y * q.y + z * q.z;
        float d = nsq + q.w - 2.0f * dot;
        if (d < d2) {
            bool c1 = d < d1, c0 = d < d0;
            d2 = c1 ? d1 : d;            i2 = c1 ? i1 : j;
            d1 = c0 ? d0 : (c1 ? d : d1); i1 = c0 ? i0 : (c1 ? j : i1);
            d0 = c0 ? d : d0;            i0 = c0 ? j : i0;
        }
    }

    const float r0 = 1.0f / (d0 + 1e-8f);
    const float r1 = 1.0f / (d1 + 1e-8f);
    const float r2 = 1.0f / (d2 + 1e-8f);
    const float inv = 1.0f / (r0 + r1 + r2);

    const int base = ((b * N1V) + n) * 3;
    g_idx[base + 0] = i0; g_idx[base + 1] = i1; g_idx[base + 2] = i2;
    g_w  [base + 0] = r0 * inv; g_w[base + 1] = r1 * inv; g_w[base + 2] = r2 * inv;
}

// ---------------- Stage 2: gather interpolation -> bf16 hi/lo, [b][k][c] ----------------
__global__ __launch_bounds__(256) void interp_kernel(const float* __restrict__ x2)
{
    const int row = blockIdx.x * 4 + (threadIdx.x >> 6);   // b*N1 + n
    const int c4  = threadIdx.x & 63;
    const int b   = row >> 12;
    const int base = row * 3;

    const int i0 = g_idx[base + 0], i1 = g_idx[base + 1], i2 = g_idx[base + 2];
    const float w0 = g_w[base + 0], w1 = g_w[base + 1], w2 = g_w[base + 2];

    const float4* xb = (const float4*)(x2 + (size_t)b * N2V * C2V);
    float4 a = xb[i0 * 64 + c4];
    float4 p = xb[i1 * 64 + c4];
    float4 q = xb[i2 * 64 + c4];

    float4 v;
    v.x = w0 * a.x + w1 * p.x + w2 * q.x;
    v.y = w0 * a.y + w1 * p.y + w2 * q.y;
    v.z = w0 * a.z + w1 * p.z + w2 * q.z;
    v.w = w0 * a.w + w1 * p.w + w2 * q.w;

    __nv_bfloat162 h0 = __floats2bfloat162_rn(v.x, v.y);
    __nv_bfloat162 h1 = __floats2bfloat162_rn(v.z, v.w);
    float lx = v.x - __bfloat162float(h0.x);
    float ly = v.y - __bfloat162float(h0.y);
    float lz = v.z - __bfloat162float(h1.x);
    float lw = v.w - __bfloat162float(h1.y);
    __nv_bfloat162 l0 = __floats2bfloat162_rn(lx, ly);
    __nv_bfloat162 l1 = __floats2bfloat162_rn(lz, lw);

    const size_t o2 = (size_t)row * 128 + c4 * 2;
    ((__nv_bfloat162*)g_Bh)[o2 + 0] = h0;
    ((__nv_bfloat162*)g_Bh)[o2 + 1] = h1;
    ((__nv_bfloat162*)g_Bl)[o2 + 0] = l0;
    ((__nv_bfloat162*)g_Bl)[o2 + 1] = l1;
}

// ---------------- Stage 3: mma.sync bf16x3 GEMM, split-K=4, 3-stage pipeline ----------------
// grid (ct=2, ot=2, z=64: b=z&15, kc=z>>4), 256 threads, 2 CTAs/SM.
// CTA tile: M=128, N=128, K=1024, k-chunks of 32; ONE barrier per k-iteration.
#define KT     32
#define NIT    32            // 1024 / KT
#define A_STR  80            // bytes per A smem row (64 data + 16 pad)
#define B_STR  272           // bytes per B smem row (256 data + 16 pad)
#define AS_SZ  (128 * A_STR) // 10240
#define BS_SZ  (KT * B_STR)  // 8704
#define STAGE  (2 * AS_SZ + 2 * BS_SZ)  // 37888
#define NSTG   3
#define SMEMT  (NSTG * STAGE)           // 113664

__device__ __forceinline__ void ldsm_x4(uint32_t* r, uint32_t addr) {
    asm volatile("ldmatrix.sync.aligned.m8n8.x4.shared.b16 {%0,%1,%2,%3}, [%4];"
                 : "=r"(r[0]), "=r"(r[1]), "=r"(r[2]), "=r"(r[3]) : "r"(addr));
}
__device__ __forceinline__ void ldsm_x4t(uint32_t* r, uint32_t addr) {
    asm volatile("ldmatrix.sync.aligned.m8n8.x4.trans.shared.b16 {%0,%1,%2,%3}, [%4];"
                 : "=r"(r[0]), "=r"(r[1]), "=r"(r[2]), "=r"(r[3]) : "r"(addr));
}
__device__ __forceinline__ void mma_bf16(float* d, const uint32_t* a, const uint32_t* b) {
    asm volatile(
        "mma.sync.aligned.m16n8k16.row.col.f32.bf16.bf16.f32 "
        "{%0,%1,%2,%3}, {%4,%5,%6,%7}, {%8,%9}, {%0,%1,%2,%3};"
        : "+f"(d[0]), "+f"(d[1]), "+f"(d[2]), "+f"(d[3])
        : "r"(a[0]), "r"(a[1]), "r"(a[2]), "r"(a[3]), "r"(b[0]), "r"(b[1]));
}
__device__ __forceinline__ void cp16(uint32_t saddr, const void* gaddr) {
    asm volatile("cp.async.cg.shared.global [%0], [%1], 16;" :: "r"(saddr), "l"(gaddr));
}

__global__ __launch_bounds__(256, 2) void gemm_mma_kernel()
{
    extern __shared__ __align__(128) char smem[];
    const uint32_t sb = smem_u32(smem);
    const int tid = threadIdx.x;
    const int wid = tid >> 5, lane = tid & 31;
    const int ct = blockIdx.x, ot = blockIdx.y;
    const int b  = blockIdx.z & 15, kc = blockIdx.z >> 4;
    const int k0 = kc * 1024;

    const __nv_bfloat16* Ahg = g_Wh + (size_t)(ot * 128) * KV + k0;
    const __nv_bfloat16* Alg = g_Wl + (size_t)(ot * 128) * KV + k0;
    const __nv_bfloat16* Bhg = g_Bh + (size_t)b * KV * C2V + (size_t)k0 * C2V + ct * 128;
    const __nv_bfloat16* Blg = g_Bl + (size_t)b * KV * C2V + (size_t)k0 * C2V + ct * 128;

    float acc[4][4][4];
    #pragma unroll
    for (int i = 0; i < 4; i++)
        #pragma unroll
        for (int j = 0; j < 4; j++)
            #pragma unroll
            for (int q = 0; q < 4; q++) acc[i][j][q] = 0.f;

    auto load_stage = [&](int it, int buf) {
        const int kb = it * KT;
        const uint32_t st = sb + buf * STAGE;
        #pragma unroll
        for (int t = 0; t < 8; t++) {
            const int ch = t * 256 + tid;
            if (ch < 512) {                       // Ah
                const int row = ch >> 2, ko = ch & 3;
                cp16(st + row * A_STR + ko * 16,
                     Ahg + (size_t)row * KV + kb + ko * 8);
            } else if (ch < 1024) {               // Al
                const int c2 = ch - 512;
                const int row = c2 >> 2, ko = c2 & 3;
                cp16(st + AS_SZ + row * A_STR + ko * 16,
                     Alg + (size_t)row * KV + kb + ko * 8);
            } else if (ch < 1536) {               // Bh
                const int c2 = ch - 1024;
                const int row = c2 >> 4, co = c2 & 15;
                cp16(st + 2 * AS_SZ + row * B_STR + co * 16,
                     Bhg + (size_t)(kb + row) * C2V + co * 8);
            } else {                              // Bl
                const int c2 = ch - 1536;
                const int row = c2 >> 4, co = c2 & 15;
                cp16(st + 2 * AS_SZ + BS_SZ + row * B_STR + co * 16,
                     Blg + (size_t)(kb + row) * C2V + co * 8);
            }
        }
        asm volatile("cp.async.commit_group;" ::: "memory");
    };

    load_stage(0, 0);
    load_stage(1, 1);

    const int wm = (wid >> 2) * 64;
    const int wn = (wid & 3) * 32;

    const int a_row = (lane & 15);
    const int a_ko  = ((lane >> 4) & 1) * 8;
    const int b_kro = (lane & 15);
    const int b_nco = wn + ((lane >> 4) & 1) * 8;

    int buf = 0;
    for (int it = 0; it < NIT; it++) {
        if (it == NIT - 1) asm volatile("cp.async.wait_group 0;" ::: "memory");
        else               asm volatile("cp.async.wait_group 1;" ::: "memory");
        __syncthreads();   // stage `buf` ready; all warps done reading stage being reloaded

        const uint32_t st = sb + buf * STAGE;
        #pragma unroll
        for (int ks = 0; ks < KT / 16; ks++) {
            const int koff = ks * 16;
            uint32_t Ah[4][4], Al[4][4];
            #pragma unroll
            for (int mi = 0; mi < 4; mi++) {
                const uint32_t arow = wm + mi * 16 + a_row;
                const uint32_t kcol = koff + a_ko;
                ldsm_x4(Ah[mi], st + arow * A_STR + kcol * 2);
                ldsm_x4(Al[mi], st + AS_SZ + arow * A_STR + kcol * 2);
            }
            uint32_t Bf[2][4];
            #pragma unroll
            for (int g = 0; g < 2; g++) {
                const uint32_t krow = koff + b_kro;
                const uint32_t ncol = b_nco + g * 16;
                ldsm_x4t(Bf[g], st + 2 * AS_SZ + krow * B_STR + ncol * 2);
            }
            #pragma unroll
            for (int mi = 0; mi < 4; mi++)
                #pragma unroll
                for (int nj = 0; nj < 4; nj++) {
                    mma_bf16(acc[mi][nj], Ah[mi], &Bf[nj >> 1][(nj & 1) * 2]);
                    mma_bf16(acc[mi][nj], Al[mi], &Bf[nj >> 1][(nj & 1) * 2]);
                }
            #pragma unroll
            for (int g = 0; g < 2; g++) {
                const uint32_t krow = koff + b_kro;
                const uint32_t ncol = b_nco + g * 16;
                ldsm_x4t(Bf[g], st + 2 * AS_SZ + BS_SZ + krow * B_STR + ncol * 2);
            }
            #pragma unroll
            for (int mi = 0; mi < 4; mi++)
                #pragma unroll
                for (int nj = 0; nj < 4; nj++)
                    mma_bf16(acc[mi][nj], Ah[mi], &Bf[nj >> 1][(nj & 1) * 2]);
        }

        if (it + 2 < NIT) {
            int nb = buf + 2; if (nb >= NSTG) nb -= NSTG;
            load_stage(it + 2, nb);
        }
        buf = (buf + 1 == NSTG) ? 0 : buf + 1;
    }

    float* pp = g_part + ((((size_t)kc * 16 + b) * 2 + ot) * 2 + ct) * 16384;
    const int lr = lane >> 2, lc = (lane & 3) * 2;
    #pragma unroll
    for (int mi = 0; mi < 4; mi++) {
        const int r0 = wm + mi * 16 + lr;
        #pragma unroll
        for (int nj = 0; nj < 4; nj++) {
            const int c = wn + nj * 8 + lc;
            *(float2*)(pp + (size_t)r0 * 128 + c)       = make_float2(acc[mi][nj][0], acc[mi][nj][1]);
            *(float2*)(pp + (size_t)(r0 + 8) * 128 + c) = make_float2(acc[mi][nj][2], acc[mi][nj][3]);
        }
    }
}

// ---------------- Stage 3b (fused): split-K reduce + bias -> g_z, plus BN partial sums ----------------
__global__ __launch_bounds__(256) void reduce_bnpart_kernel(const float* __restrict__ b1)
{
    const int c = threadIdx.x;
    const int r0 = blockIdx.x * 32;
    float s = 0.f, sq = 0.f;
    #pragma unroll 4
    for (int r = r0; r < r0 + 32; r++) {
        const int b = r >> 8, o = r & 255;
        const size_t inner = ((size_t)(o >> 7) * 2 + (c >> 7)) * 16384
                           + (size_t)(o & 127) * 128 + (c & 127);
        float v = b1[o];
        #pragma unroll
        for (int kc = 0; kc < 4; kc++)
            v += g_part[((size_t)kc * 16 + b) * 65536 + inner];
        g_z[(size_t)r * C2V + c] = v;
        s += v; sq += v * v;
    }
    g_psum[blockIdx.x * C2V + c] = s;
    g_psq [blockIdx.x * C2V + c] = sq;
}

// ---------------- Stage 4: BN finalize + apply ----------------
__global__ __launch_bounds__(256) void bn_final_kernel(
    const float* __restrict__ gamma, const float* __restrict__ beta)
{
    const int c = threadIdx.x;
    float s = 0.f, sq = 0.f;
    #pragma unroll
    for (int i = 0; i < 128; i++) { s += g_psum[i * C2V + c]; sq += g_psq[i * C2V + c]; }
    const float mean = s * (1.0f / 4096.0f);
    const float var  = sq * (1.0f / 4096.0f) - mean * mean;
    const float rstd = rsqrtf(var + 1e-5f);
    const float a = gamma[c] * rstd;
    g_scale[c] = a;
    g_shift[c] = beta[c] - mean * a;
}

__global__ __launch_bounds__(256) void bn_apply_kernel(float* __restrict__ out)
{
    const int i = blockIdx.x * 256 + threadIdx.x;
    const int c = i & 255;
    float v = fmaf(g_z[i], g_scale[c], g_shift[c]);
    out[i] = fmaxf(v, 0.0f);
}

// ---------------- launch ----------------
extern "C" void kernel_launch(void* const* d_in, const int* in_sizes, int n_in,
                              void* d_out, int out_size)
{
    const float* x2    = (const float*)d_in[1];
    const float* xyz1  = (const float*)d_in[2];
    const float* xyz2  = (const float*)d_in[3];
    const float* W1    = (const float*)d_in[4];
    const float* b1    = (const float*)d_in[5];
    const float* gamma = (const float*)d_in[6];
    const float* beta  = (const float*)d_in[7];
    float* out = (float*)d_out;

    static bool attr_set = false;
    if (!attr_set) {
        cudaFuncSetAttribute(gemm_mma_kernel,
                             cudaFuncAttributeMaxDynamicSharedMemorySize, SMEMT);
        attr_set = true;
    }

    top3_kernel<<<BB * 16, 256>>>(xyz1, xyz2);
    wsplit_kernel<<<(OUTV * KV) / 256, 256>>>(W1);
    interp_kernel<<<(BB * N1V) / 4, 256>>>(x2);

    dim3 ggrid(2, 2, 64);
    gemm_mma_kernel<<<ggrid, 256, SMEMT>>>();

    reduce_bnpart_kernel<<<128, 256>>>(b1);
    bn_final_kernel<<<1, 256>>>(gamma, beta);
    bn_apply_kernel<<<(BB * OUTV * C2V) / 256, 256>>>(out);
}